// round 5
// baseline (speedup 1.0000x reference)
#include <cuda_runtime.h>

#define NN 200000
#define NE 600000
#define NG 10000
#define FIN 32
#define HD 128
#define BN_EPS 1e-5f

// ---------------- scratch (no allocations allowed) ----------------
__device__ float g_scr_a[NN * FIN];        // x + agg(x)
__device__ float g_h1[NN * HD];            // layer a output
__device__ float g_scr_b[NN * HD];         // h1 + agg(h1)
__device__ float g_h2[NN * HD];            // layer b output
__device__ float g_scr_c[NN * HD];         // h2 + agg(h2)
__device__ float g_hg[NG * HD];            // pooled graph features

// ---------------- init: copy x -> scr_a, zero hg ----------------
__global__ void init_kernel(const float* __restrict__ x) {
    int i = blockIdx.x * blockDim.x + threadIdx.x;
    const int ncopy = NN * FIN / 4;   // 1.6M float4
    const int nzero = NG * HD / 4;    // 320k float4
    if (i < ncopy) {
        ((float4*)g_scr_a)[i] = ((const float4*)x)[i];
    } else {
        int j = i - ncopy;
        if (j < nzero) ((float4*)g_hg)[j] = make_float4(0.f, 0.f, 0.f, 0.f);
    }
}

// ---------------- scatter-add: scr[dst] += h[src] ----------------
// edge_index arrives as int32 (harness converts int64 -> int32).
template <int DIM>
__global__ void scatter_kernel(const int* __restrict__ ei,
                               const float* __restrict__ h,
                               float* __restrict__ scr) {
    const int CH = DIM / 4;
    long long id = (long long)blockIdx.x * blockDim.x + threadIdx.x;
    int e = (int)(id / CH);
    int c = (int)(id % CH);
    if (e >= NE) return;
    int src = __ldg(&ei[e]);
    int dst = __ldg(&ei[NE + e]);
    float4 v = __ldg(((const float4*)(h + (size_t)src * DIM)) + c);
    atomicAdd(((float4*)(scr + (size_t)dst * DIM)) + c, v);
}

// ---------------- fused GIN layer ----------------
__device__ __forceinline__ void fma4(float4& acc, float s, const float4& wv) {
    acc.x = fmaf(s, wv.x, acc.x);
    acc.y = fmaf(s, wv.y, acc.y);
    acc.z = fmaf(s, wv.z, acc.z);
    acc.w = fmaf(s, wv.w, acc.w);
}

template <int IN>
__device__ __forceinline__ void gemm_tile(const float* __restrict__ A,
                                          const float* __restrict__ Ws,
                                          int ng, int cg, float4 acc[8]) {
#pragma unroll 4
    for (int k0 = 0; k0 < IN; k0 += 4) {
        float4 w0 = *(const float4*)(Ws + (k0 + 0) * HD + cg * 4);
        float4 w1 = *(const float4*)(Ws + (k0 + 1) * HD + cg * 4);
        float4 w2 = *(const float4*)(Ws + (k0 + 2) * HD + cg * 4);
        float4 w3 = *(const float4*)(Ws + (k0 + 3) * HD + cg * 4);
#pragma unroll
        for (int i = 0; i < 8; i++) {
            float4 a = *(const float4*)(A + (ng * 8 + i) * IN + k0);
            fma4(acc[i], a.x, w0);
            fma4(acc[i], a.y, w1);
            fma4(acc[i], a.z, w2);
            fma4(acc[i], a.w, w3);
        }
    }
}

// MODE 0: write h_next and scr_next.  MODE 1: pool into g_hg (layer c).
template <int IN, int MODE>
__global__ void gin_layer_kernel(const float* __restrict__ in,
                                 const float* __restrict__ W1,
                                 const float* __restrict__ b1,
                                 const float* __restrict__ gg,
                                 const float* __restrict__ be,
                                 const float* __restrict__ rm,
                                 const float* __restrict__ rv,
                                 const float* __restrict__ W2,
                                 const float* __restrict__ b2,
                                 float* __restrict__ h_next,
                                 float* __restrict__ scr_next,
                                 const int* __restrict__ batch) {
    extern __shared__ float sm[];
    float* As  = sm;                    // 64 * IN
    float* W1s = As + 64 * IN;          // IN * 128
    float* W2s = W1s + IN * HD;         // 128 * 128
    float* Z1  = W2s + HD * HD;         // 64 * 128

    int t = threadIdx.x;                // 256 threads
    int cg = t & 31;                    // cols 4*cg .. 4*cg+3
    int ng = t >> 5;                    // nodes 8*ng .. 8*ng+7
    int base = blockIdx.x * 64;

    // stage weights
    for (int i = t; i < IN * HD / 4; i += 256)
        ((float4*)W1s)[i] = __ldg(((const float4*)W1) + i);
    for (int i = t; i < HD * HD / 4; i += 256)
        ((float4*)W2s)[i] = __ldg(((const float4*)W2) + i);
    // stage input tile (grid is exact: 3125*64 == 200000)
    for (int i = t; i < 64 * IN / 4; i += 256) {
        int node = base + i / (IN / 4);
        int c4 = i % (IN / 4);
        ((float4*)As)[i] = __ldg(((const float4*)(in + (size_t)node * IN)) + c4);
    }
    __syncthreads();

    // ---- phase 1: Z1 = relu(BN(As @ W1 + b1)) ----
    float4 acc[8];
#pragma unroll
    for (int i = 0; i < 8; i++) acc[i] = make_float4(0.f, 0.f, 0.f, 0.f);
    gemm_tile<IN>(As, W1s, ng, cg, acc);

    {
        float4 g4  = __ldg(((const float4*)gg) + cg);
        float4 rv4 = __ldg(((const float4*)rv) + cg);
        float4 rm4 = __ldg(((const float4*)rm) + cg);
        float4 be4 = __ldg(((const float4*)be) + cg);
        float4 b14 = __ldg(((const float4*)b1) + cg);
        float4 mul, add;
        mul.x = g4.x * rsqrtf(rv4.x + BN_EPS);
        mul.y = g4.y * rsqrtf(rv4.y + BN_EPS);
        mul.z = g4.z * rsqrtf(rv4.z + BN_EPS);
        mul.w = g4.w * rsqrtf(rv4.w + BN_EPS);
        add.x = (b14.x - rm4.x) * mul.x + be4.x;
        add.y = (b14.y - rm4.y) * mul.y + be4.y;
        add.z = (b14.z - rm4.z) * mul.z + be4.z;
        add.w = (b14.w - rm4.w) * mul.w + be4.w;
#pragma unroll
        for (int i = 0; i < 8; i++) {
            float4 z;
            z.x = fmaxf(fmaf(acc[i].x, mul.x, add.x), 0.f);
            z.y = fmaxf(fmaf(acc[i].y, mul.y, add.y), 0.f);
            z.z = fmaxf(fmaf(acc[i].z, mul.z, add.z), 0.f);
            z.w = fmaxf(fmaf(acc[i].w, mul.w, add.w), 0.f);
            *(float4*)(Z1 + (ng * 8 + i) * HD + cg * 4) = z;
        }
    }
    __syncthreads();

    // ---- phase 2: out = relu(Z1 @ W2 + b2) ----
#pragma unroll
    for (int i = 0; i < 8; i++) acc[i] = make_float4(0.f, 0.f, 0.f, 0.f);
    gemm_tile<HD>(Z1, W2s, ng, cg, acc);

    float4 b24 = __ldg(((const float4*)b2) + cg);

    if (MODE == 0) {
#pragma unroll
        for (int i = 0; i < 8; i++) {
            int node = base + ng * 8 + i;
            float4 r;
            r.x = fmaxf(acc[i].x + b24.x, 0.f);
            r.y = fmaxf(acc[i].y + b24.y, 0.f);
            r.z = fmaxf(acc[i].z + b24.z, 0.f);
            r.w = fmaxf(acc[i].w + b24.w, 0.f);
            *(float4*)(h_next + (size_t)node * HD + cg * 4) = r;
            *(float4*)(scr_next + (size_t)node * HD + cg * 4) = r;
        }
    } else {
        // pool into g_hg with run-length merged atomics (batch is sorted)
        int prev = -1;
        float4 sum = make_float4(0.f, 0.f, 0.f, 0.f);
#pragma unroll
        for (int i = 0; i < 8; i++) {
            int node = base + ng * 8 + i;
            float4 r;
            r.x = fmaxf(acc[i].x + b24.x, 0.f);
            r.y = fmaxf(acc[i].y + b24.y, 0.f);
            r.z = fmaxf(acc[i].z + b24.z, 0.f);
            r.w = fmaxf(acc[i].w + b24.w, 0.f);
            int bg = __ldg(&batch[node]);
            if (bg == prev) {
                sum.x += r.x; sum.y += r.y; sum.z += r.z; sum.w += r.w;
            } else {
                if (prev >= 0)
                    atomicAdd((float4*)(g_hg + (size_t)prev * HD + cg * 4), sum);
                prev = bg;
                sum = r;
            }
        }
        if (prev >= 0)
            atomicAdd((float4*)(g_hg + (size_t)prev * HD + cg * 4), sum);
    }
}

// ---------------- pooled MLP head ----------------
__global__ void pool_head_kernel(const float* __restrict__ lw1,
                                 const float* __restrict__ lb1,
                                 const float* __restrict__ lw2,
                                 const float* __restrict__ lb2,
                                 float* __restrict__ out) {
    extern __shared__ float psm[];
    float* Ws   = psm;              // 128*128
    float* hrow = psm + HD * HD;    // 128
    float* redb = hrow + HD;        // 4

    int t = threadIdx.x;            // 128 threads, t = output column
    for (int i = t; i < HD * HD / 4; i += 128)
        ((float4*)Ws)[i] = __ldg(((const float4*)lw1) + i);
    float lb1t = __ldg(&lb1[t]);
    float w2t  = __ldg(&lw2[t]);
    float lb2v = __ldg(&lb2[0]);
    __syncthreads();

    int gbase = blockIdx.x * 8;
    for (int gi = 0; gi < 8; gi++) {
        int g = gbase + gi;
        hrow[t] = g_hg[(size_t)g * HD + t];
        __syncthreads();
        float a = 0.f;
#pragma unroll
        for (int k = 0; k < HD; k++)
            a = fmaf(hrow[k], Ws[k * HD + t], a);
        float p = fmaxf(a + lb1t, 0.f) * w2t;
#pragma unroll
        for (int o = 16; o > 0; o >>= 1)
            p += __shfl_xor_sync(0xffffffffu, p, o);
        if ((t & 31) == 0) redb[t >> 5] = p;
        __syncthreads();
        if (t == 0)
            out[g] = redb[0] + redb[1] + redb[2] + redb[3] + lb2v;
        __syncthreads();
    }
}

// ---------------- launch ----------------
extern "C" void kernel_launch(void* const* d_in, const int* in_sizes, int n_in,
                              void* d_out, int out_size) {
    const float* x      = (const float*)d_in[0];
    const int* ei       = (const int*)d_in[1];    // int32 (harness converts int64)
    const int* batch    = (const int*)d_in[2];    // int32
    const float* W1a = (const float*)d_in[3];
    const float* b1a = (const float*)d_in[4];
    const float* ga  = (const float*)d_in[5];
    const float* bea = (const float*)d_in[6];
    const float* rma = (const float*)d_in[7];
    const float* rva = (const float*)d_in[8];
    const float* W2a = (const float*)d_in[9];
    const float* b2a = (const float*)d_in[10];
    const float* W1b = (const float*)d_in[11];
    const float* b1b = (const float*)d_in[12];
    const float* gb  = (const float*)d_in[13];
    const float* beb = (const float*)d_in[14];
    const float* rmb = (const float*)d_in[15];
    const float* rvb = (const float*)d_in[16];
    const float* W2b = (const float*)d_in[17];
    const float* b2b = (const float*)d_in[18];
    const float* W1c = (const float*)d_in[19];
    const float* b1c = (const float*)d_in[20];
    const float* gc  = (const float*)d_in[21];
    const float* bec = (const float*)d_in[22];
    const float* rmc = (const float*)d_in[23];
    const float* rvc = (const float*)d_in[24];
    const float* W2c = (const float*)d_in[25];
    const float* b2c = (const float*)d_in[26];
    const float* lw1 = (const float*)d_in[27];
    const float* lb1 = (const float*)d_in[28];
    const float* lw2 = (const float*)d_in[29];
    const float* lb2 = (const float*)d_in[30];
    float* out = (float*)d_out;

    // scratch pointers
    float *scr_a, *h1, *scr_b, *h2, *scr_c;
    cudaGetSymbolAddress((void**)&scr_a, g_scr_a);
    cudaGetSymbolAddress((void**)&h1,    g_h1);
    cudaGetSymbolAddress((void**)&scr_b, g_scr_b);
    cudaGetSymbolAddress((void**)&h2,    g_h2);
    cudaGetSymbolAddress((void**)&scr_c, g_scr_c);

    const int smem_a = (64 * FIN + FIN * HD + HD * HD + 64 * HD) * 4;  // 122880
    const int smem_h = (64 * HD + HD * HD + HD * HD + 64 * HD) * 4;    // 196608
    const int smem_p = (HD * HD + HD + 4) * 4;                         // ~66 KB

    cudaFuncSetAttribute(gin_layer_kernel<FIN, 0>,
                         cudaFuncAttributeMaxDynamicSharedMemorySize, smem_a);
    cudaFuncSetAttribute(gin_layer_kernel<HD, 0>,
                         cudaFuncAttributeMaxDynamicSharedMemorySize, smem_h);
    cudaFuncSetAttribute(gin_layer_kernel<HD, 1>,
                         cudaFuncAttributeMaxDynamicSharedMemorySize, smem_h);
    cudaFuncSetAttribute(pool_head_kernel,
                         cudaFuncAttributeMaxDynamicSharedMemorySize, smem_p);

    // 1. init: scr_a = x, hg = 0
    init_kernel<<<7500, 256>>>(x);

    // 2. scatter x into scr_a (32 dims): 600000*8 threads
    scatter_kernel<FIN><<<18750, 256>>>(ei, x, scr_a);

    // 3. layer a
    gin_layer_kernel<FIN, 0><<<NN / 64, 256, smem_a>>>(
        scr_a, W1a, b1a, ga, bea, rma, rva, W2a, b2a, h1, scr_b, nullptr);

    // 4. scatter h1 into scr_b (128 dims): 600000*32 threads
    scatter_kernel<HD><<<75000, 256>>>(ei, h1, scr_b);

    // 5. layer b
    gin_layer_kernel<HD, 0><<<NN / 64, 256, smem_h>>>(
        scr_b, W1b, b1b, gb, beb, rmb, rvb, W2b, b2b, h2, scr_c, nullptr);

    // 6. scatter h2 into scr_c
    scatter_kernel<HD><<<75000, 256>>>(ei, h2, scr_c);

    // 7. layer c + fused global_add_pool
    gin_layer_kernel<HD, 1><<<NN / 64, 256, smem_h>>>(
        scr_c, W1c, b1c, gc, bec, rmc, rvc, W2c, b2c, nullptr, nullptr, batch);

    // 8. head MLP
    pool_head_kernel<<<NG / 8, 128, smem_p>>>(lw1, lb1, lw2, lb2, out);
}

// round 7
// speedup vs baseline: 1.0104x; 1.0104x over previous
#include <cuda_runtime.h>

#define NN 200000
#define NE 600000
#define NG 10000
#define FIN 32
#define HD 128
#define BN_EPS 1e-5f

// ---------------- scratch (no allocations allowed) ----------------
__device__ float g_scr_a[NN * FIN];        // x + agg(x)
__device__ float g_h1[NN * HD];            // layer a output
__device__ float g_scr_b[NN * HD];         // h1 + agg(h1)
__device__ float g_h2[NN * HD];            // layer b output
__device__ float g_scr_c[NN * HD];         // h2 + agg(h2)
__device__ float g_hg[NG * HD];            // pooled graph features

// ---------------- packed fp32x2 helpers (Blackwell FFMA2 path) ----------------
__device__ __forceinline__ unsigned long long dup2(float s) {
    unsigned long long r;
    asm("mov.b64 %0, {%1, %1};" : "=l"(r) : "r"(__float_as_uint(s)));
    return r;
}
__device__ __forceinline__ void ffma2(unsigned long long& d,
                                      unsigned long long a,
                                      unsigned long long b) {
    asm("fma.rn.f32x2 %0, %1, %2, %0;" : "+l"(d) : "l"(a), "l"(b));
}
__device__ __forceinline__ float2 unpack2(unsigned long long v) {
    unsigned int lo, hi;
    asm("mov.b64 {%0, %1}, %2;" : "=r"(lo), "=r"(hi) : "l"(v));
    return make_float2(__uint_as_float(lo), __uint_as_float(hi));
}

// ---------------- init: copy x -> scr_a, zero hg ----------------
__global__ void init_kernel(const float* __restrict__ x) {
    int i = blockIdx.x * blockDim.x + threadIdx.x;
    const int ncopy = NN * FIN / 4;   // 1.6M float4
    const int nzero = NG * HD / 4;    // 320k float4
    if (i < ncopy) {
        ((float4*)g_scr_a)[i] = ((const float4*)x)[i];
    } else {
        int j = i - ncopy;
        if (j < nzero) ((float4*)g_hg)[j] = make_float4(0.f, 0.f, 0.f, 0.f);
    }
}

// ---------------- scatter-add: scr[dst] += h[src] ----------------
template <int DIM>
__global__ void scatter_kernel(const int* __restrict__ ei,
                               const float* __restrict__ h,
                               float* __restrict__ scr) {
    const int CH = DIM / 4;
    long long id = (long long)blockIdx.x * blockDim.x + threadIdx.x;
    int e = (int)(id / CH);
    int c = (int)(id % CH);
    if (e >= NE) return;
    int src = __ldg(&ei[e]);
    int dst = __ldg(&ei[NE + e]);
    float4 v = __ldg(((const float4*)(h + (size_t)src * DIM)) + c);
    atomicAdd(((float4*)(scr + (size_t)dst * DIM)) + c, v);
}

// ---------------- packed GEMM tile: 8 nodes x 4 cols per thread ----------------
template <int IN>
__device__ __forceinline__ void gemm_tile2(const float* __restrict__ A,
                                           const float* __restrict__ Ws,
                                           int ng, int cg,
                                           unsigned long long acc[8][2]) {
#pragma unroll 4
    for (int k0 = 0; k0 < IN; k0 += 4) {
        ulonglong2 w0 = *(const ulonglong2*)(Ws + (k0 + 0) * HD + cg * 4);
        ulonglong2 w1 = *(const ulonglong2*)(Ws + (k0 + 1) * HD + cg * 4);
        ulonglong2 w2 = *(const ulonglong2*)(Ws + (k0 + 2) * HD + cg * 4);
        ulonglong2 w3 = *(const ulonglong2*)(Ws + (k0 + 3) * HD + cg * 4);
#pragma unroll
        for (int i = 0; i < 8; i++) {
            float4 a = *(const float4*)(A + (ng * 8 + i) * IN + k0);
            unsigned long long a0 = dup2(a.x);
            unsigned long long a1 = dup2(a.y);
            unsigned long long a2 = dup2(a.z);
            unsigned long long a3 = dup2(a.w);
            ffma2(acc[i][0], a0, w0.x); ffma2(acc[i][1], a0, w0.y);
            ffma2(acc[i][0], a1, w1.x); ffma2(acc[i][1], a1, w1.y);
            ffma2(acc[i][0], a2, w2.x); ffma2(acc[i][1], a2, w2.y);
            ffma2(acc[i][0], a3, w3.x); ffma2(acc[i][1], a3, w3.y);
        }
    }
}

// MODE 0: write h_next and scr_next.  MODE 1: pool into g_hg (layer c).
template <int IN, int MODE>
__global__ void gin_layer_kernel(const float* __restrict__ in,
                                 const float* __restrict__ W1,
                                 const float* __restrict__ b1,
                                 const float* __restrict__ gg,
                                 const float* __restrict__ be,
                                 const float* __restrict__ rm,
                                 const float* __restrict__ rv,
                                 const float* __restrict__ W2,
                                 const float* __restrict__ b2,
                                 float* __restrict__ h_next,
                                 float* __restrict__ scr_next,
                                 const int* __restrict__ batch) {
    extern __shared__ float sm[];
    float* As  = sm;                    // 64 * IN
    float* W1s = As + 64 * IN;          // IN * 128
    float* W2s = W1s + IN * HD;         // 128 * 128
    float* Z1  = W2s + HD * HD;         // 64 * 128

    int t = threadIdx.x;                // 256 threads
    int cg = t & 31;                    // cols 4*cg .. 4*cg+3
    int ng = t >> 5;                    // nodes 8*ng .. 8*ng+7
    int base = blockIdx.x * 64;

    // stage weights
    for (int i = t; i < IN * HD / 4; i += 256)
        ((float4*)W1s)[i] = __ldg(((const float4*)W1) + i);
    for (int i = t; i < HD * HD / 4; i += 256)
        ((float4*)W2s)[i] = __ldg(((const float4*)W2) + i);
    // stage input tile (grid is exact: 3125*64 == 200000)
    for (int i = t; i < 64 * IN / 4; i += 256) {
        int node = base + i / (IN / 4);
        int c4 = i % (IN / 4);
        ((float4*)As)[i] = __ldg(((const float4*)(in + (size_t)node * IN)) + c4);
    }
    __syncthreads();

    // ---- phase 1: Z1 = relu(BN(As @ W1 + b1)) ----
    unsigned long long acc[8][2];
#pragma unroll
    for (int i = 0; i < 8; i++) { acc[i][0] = 0ull; acc[i][1] = 0ull; }
    gemm_tile2<IN>(As, W1s, ng, cg, acc);

    {
        float4 g4  = __ldg(((const float4*)gg) + cg);
        float4 rv4 = __ldg(((const float4*)rv) + cg);
        float4 rm4 = __ldg(((const float4*)rm) + cg);
        float4 be4 = __ldg(((const float4*)be) + cg);
        float4 b14 = __ldg(((const float4*)b1) + cg);
        float4 mul, add;
        mul.x = g4.x * rsqrtf(rv4.x + BN_EPS);
        mul.y = g4.y * rsqrtf(rv4.y + BN_EPS);
        mul.z = g4.z * rsqrtf(rv4.z + BN_EPS);
        mul.w = g4.w * rsqrtf(rv4.w + BN_EPS);
        add.x = (b14.x - rm4.x) * mul.x + be4.x;
        add.y = (b14.y - rm4.y) * mul.y + be4.y;
        add.z = (b14.z - rm4.z) * mul.z + be4.z;
        add.w = (b14.w - rm4.w) * mul.w + be4.w;
#pragma unroll
        for (int i = 0; i < 8; i++) {
            float2 lo = unpack2(acc[i][0]);
            float2 hi = unpack2(acc[i][1]);
            float4 z;
            z.x = fmaxf(fmaf(lo.x, mul.x, add.x), 0.f);
            z.y = fmaxf(fmaf(lo.y, mul.y, add.y), 0.f);
            z.z = fmaxf(fmaf(hi.x, mul.z, add.z), 0.f);
            z.w = fmaxf(fmaf(hi.y, mul.w, add.w), 0.f);
            *(float4*)(Z1 + (ng * 8 + i) * HD + cg * 4) = z;
        }
    }
    __syncthreads();

    // ---- phase 2: out = relu(Z1 @ W2 + b2) ----
#pragma unroll
    for (int i = 0; i < 8; i++) { acc[i][0] = 0ull; acc[i][1] = 0ull; }
    gemm_tile2<HD>(Z1, W2s, ng, cg, acc);

    float4 b24 = __ldg(((const float4*)b2) + cg);

    if (MODE == 0) {
#pragma unroll
        for (int i = 0; i < 8; i++) {
            int node = base + ng * 8 + i;
            float2 lo = unpack2(acc[i][0]);
            float2 hi = unpack2(acc[i][1]);
            float4 r;
            r.x = fmaxf(lo.x + b24.x, 0.f);
            r.y = fmaxf(lo.y + b24.y, 0.f);
            r.z = fmaxf(hi.x + b24.z, 0.f);
            r.w = fmaxf(hi.y + b24.w, 0.f);
            *(float4*)(h_next + (size_t)node * HD + cg * 4) = r;
            *(float4*)(scr_next + (size_t)node * HD + cg * 4) = r;
        }
    } else {
        // pool into g_hg with run-length merged atomics (batch is sorted)
        int prev = -1;
        float4 sum = make_float4(0.f, 0.f, 0.f, 0.f);
#pragma unroll
        for (int i = 0; i < 8; i++) {
            int node = base + ng * 8 + i;
            float2 lo = unpack2(acc[i][0]);
            float2 hi = unpack2(acc[i][1]);
            float4 r;
            r.x = fmaxf(lo.x + b24.x, 0.f);
            r.y = fmaxf(lo.y + b24.y, 0.f);
            r.z = fmaxf(hi.x + b24.z, 0.f);
            r.w = fmaxf(hi.y + b24.w, 0.f);
            int bg = __ldg(&batch[node]);
            if (bg == prev) {
                sum.x += r.x; sum.y += r.y; sum.z += r.z; sum.w += r.w;
            } else {
                if (prev >= 0)
                    atomicAdd((float4*)(g_hg + (size_t)prev * HD + cg * 4), sum);
                prev = bg;
                sum = r;
            }
        }
        if (prev >= 0)
            atomicAdd((float4*)(g_hg + (size_t)prev * HD + cg * 4), sum);
    }
}

// ---------------- pooled MLP head ----------------
__global__ void pool_head_kernel(const float* __restrict__ lw1,
                                 const float* __restrict__ lb1,
                                 const float* __restrict__ lw2,
                                 const float* __restrict__ lb2,
                                 float* __restrict__ out) {
    extern __shared__ float psm[];
    float* Ws   = psm;              // 128*128
    float* hrow = psm + HD * HD;    // 128
    float* redb = hrow + HD;        // 4

    int t = threadIdx.x;            // 128 threads, t = output column
    for (int i = t; i < HD * HD / 4; i += 128)
        ((float4*)Ws)[i] = __ldg(((const float4*)lw1) + i);
    float lb1t = __ldg(&lb1[t]);
    float w2t  = __ldg(&lw2[t]);
    float lb2v = __ldg(&lb2[0]);
    __syncthreads();

    int gbase = blockIdx.x * 8;
    for (int gi = 0; gi < 8; gi++) {
        int g = gbase + gi;
        hrow[t] = g_hg[(size_t)g * HD + t];
        __syncthreads();
        float a = 0.f;
#pragma unroll
        for (int k = 0; k < HD; k++)
            a = fmaf(hrow[k], Ws[k * HD + t], a);
        float p = fmaxf(a + lb1t, 0.f) * w2t;
#pragma unroll
        for (int o = 16; o > 0; o >>= 1)
            p += __shfl_xor_sync(0xffffffffu, p, o);
        if ((t & 31) == 0) redb[t >> 5] = p;
        __syncthreads();
        if (t == 0)
            out[g] = redb[0] + redb[1] + redb[2] + redb[3] + lb2v;
        __syncthreads();
    }
}

// ---------------- launch ----------------
extern "C" void kernel_launch(void* const* d_in, const int* in_sizes, int n_in,
                              void* d_out, int out_size) {
    const float* x      = (const float*)d_in[0];
    const int* ei       = (const int*)d_in[1];    // int32
    const int* batch    = (const int*)d_in[2];    // int32
    const float* W1a = (const float*)d_in[3];
    const float* b1a = (const float*)d_in[4];
    const float* ga  = (const float*)d_in[5];
    const float* bea = (const float*)d_in[6];
    const float* rma = (const float*)d_in[7];
    const float* rva = (const float*)d_in[8];
    const float* W2a = (const float*)d_in[9];
    const float* b2a = (const float*)d_in[10];
    const float* W1b = (const float*)d_in[11];
    const float* b1b = (const float*)d_in[12];
    const float* gb  = (const float*)d_in[13];
    const float* beb = (const float*)d_in[14];
    const float* rmb = (const float*)d_in[15];
    const float* rvb = (const float*)d_in[16];
    const float* W2b = (const float*)d_in[17];
    const float* b2b = (const float*)d_in[18];
    const float* W1c = (const float*)d_in[19];
    const float* b1c = (const float*)d_in[20];
    const float* gc  = (const float*)d_in[21];
    const float* bec = (const float*)d_in[22];
    const float* rmc = (const float*)d_in[23];
    const float* rvc = (const float*)d_in[24];
    const float* W2c = (const float*)d_in[25];
    const float* b2c = (const float*)d_in[26];
    const float* lw1 = (const float*)d_in[27];
    const float* lb1 = (const float*)d_in[28];
    const float* lw2 = (const float*)d_in[29];
    const float* lb2 = (const float*)d_in[30];
    float* out = (float*)d_out;

    // scratch pointers
    float *scr_a, *h1, *scr_b, *h2, *scr_c;
    cudaGetSymbolAddress((void**)&scr_a, g_scr_a);
    cudaGetSymbolAddress((void**)&h1,    g_h1);
    cudaGetSymbolAddress((void**)&scr_b, g_scr_b);
    cudaGetSymbolAddress((void**)&h2,    g_h2);
    cudaGetSymbolAddress((void**)&scr_c, g_scr_c);

    const int smem_a = (64 * FIN + FIN * HD + HD * HD + 64 * HD) * 4;  // 122880
    const int smem_h = (64 * HD + HD * HD + HD * HD + 64 * HD) * 4;    // 196608
    const int smem_p = (HD * HD + HD + 4) * 4;                         // ~66 KB

    cudaFuncSetAttribute(gin_layer_kernel<FIN, 0>,
                         cudaFuncAttributeMaxDynamicSharedMemorySize, smem_a);
    cudaFuncSetAttribute(gin_layer_kernel<HD, 0>,
                         cudaFuncAttributeMaxDynamicSharedMemorySize, smem_h);
    cudaFuncSetAttribute(gin_layer_kernel<HD, 1>,
                         cudaFuncAttributeMaxDynamicSharedMemorySize, smem_h);
    cudaFuncSetAttribute(pool_head_kernel,
                         cudaFuncAttributeMaxDynamicSharedMemorySize, smem_p);

    // 1. init: scr_a = x, hg = 0
    init_kernel<<<7500, 256>>>(x);

    // 2. scatter x into scr_a (32 dims)
    scatter_kernel<FIN><<<18750, 256>>>(ei, x, scr_a);

    // 3. layer a
    gin_layer_kernel<FIN, 0><<<NN / 64, 256, smem_a>>>(
        scr_a, W1a, b1a, ga, bea, rma, rva, W2a, b2a, h1, scr_b, nullptr);

    // 4. scatter h1 into scr_b (128 dims)
    scatter_kernel<HD><<<75000, 256>>>(ei, h1, scr_b);

    // 5. layer b
    gin_layer_kernel<HD, 0><<<NN / 64, 256, smem_h>>>(
        scr_b, W1b, b1b, gb, beb, rmb, rvb, W2b, b2b, h2, scr_c, nullptr);

    // 6. scatter h2 into scr_c
    scatter_kernel<HD><<<75000, 256>>>(ei, h2, scr_c);

    // 7. layer c + fused global_add_pool
    gin_layer_kernel<HD, 1><<<NN / 64, 256, smem_h>>>(
        scr_c, W1c, b1c, gc, bec, rmc, rvc, W2c, b2c, nullptr, nullptr, batch);

    // 8. head MLP
    pool_head_kernel<<<NG / 8, 128, smem_p>>>(lw1, lb1, lw2, lb2, out);
}

// round 13
// speedup vs baseline: 2.0027x; 1.9820x over previous
#include <cuda_runtime.h>
#include <cuda_bf16.h>
#include <cstdint>

#define NN 200000
#define NE 600000
#define NG 10000
#define FIN 32
#define HD 128
#define BN_EPS 1e-5f
#define NBLK 1563   // ceil(200000/128)

// smem layout constants (bytes)
#define TILEB 34816          // 128 rows * 272 B (136 bf16 stride)
#define OFF_ZH 2048
#define OFF_ZL (OFF_ZH + TILEB)
#define OFF_W1H (OFF_ZL + TILEB)
#define OFF_W1L (OFF_W1H + TILEB)
#define OFF_W2H (OFF_W1L + TILEB)
#define OFF_W2L (OFF_W2H + TILEB)
#define SMEM_TOTAL (OFF_W2L + TILEB)   // 210944 B

// ---------------- scratch (no allocations allowed) ----------------
__device__ float g_scr_a[NN * FIN];
__device__ float g_h1[NN * HD];
__device__ float g_scr_b[NN * HD];
__device__ float g_h2[NN * HD];
__device__ float g_scr_c[NN * HD];
__device__ float g_hg[NG * HD];

// W^T bf16 planes [hi=0/lo=1][n*K + k] — 16B-aligned: cp.async.cg src requires it
__device__ __align__(16) __nv_bfloat16 g_W1a[2][128 * 32];
__device__ __align__(16) __nv_bfloat16 g_W2a[2][128 * 128];
__device__ __align__(16) __nv_bfloat16 g_W1b[2][128 * 128];
__device__ __align__(16) __nv_bfloat16 g_W2b[2][128 * 128];
__device__ __align__(16) __nv_bfloat16 g_W1c[2][128 * 128];
__device__ __align__(16) __nv_bfloat16 g_W2c[2][128 * 128];

// ---------------- helpers ----------------
__device__ __forceinline__ uint32_t smem_u32(const void* p) {
    uint32_t a;
    asm("{ .reg .u64 t; cvta.to.shared.u64 t, %1; cvt.u32.u64 %0, t; }" : "=r"(a) : "l"(p));
    return a;
}
__device__ __forceinline__ void ldsm4(uint32_t* r, uint32_t a) {
    asm volatile("ldmatrix.sync.aligned.m8n8.x4.shared.b16 {%0,%1,%2,%3}, [%4];"
                 : "=r"(r[0]), "=r"(r[1]), "=r"(r[2]), "=r"(r[3]) : "r"(a));
}
__device__ __forceinline__ void mma16816(float* c, const uint32_t* a, uint32_t b0, uint32_t b1) {
    asm volatile("mma.sync.aligned.m16n8k16.row.col.f32.bf16.bf16.f32 "
                 "{%0,%1,%2,%3}, {%4,%5,%6,%7}, {%8,%9}, {%0,%1,%2,%3};"
                 : "+f"(c[0]), "+f"(c[1]), "+f"(c[2]), "+f"(c[3])
                 : "r"(a[0]), "r"(a[1]), "r"(a[2]), "r"(a[3]), "r"(b0), "r"(b1));
}
#define CP16(dst, src) \
    asm volatile("cp.async.cg.shared.global [%0], [%1], 16;" :: "r"(dst), "l"(src) : "memory")
#define CP_COMMIT() asm volatile("cp.async.commit_group;" ::: "memory")
#define CP_WAIT1()  asm volatile("cp.async.wait_group 1;" ::: "memory")
#define CP_WAIT0()  asm volatile("cp.async.wait_group 0;" ::: "memory")

__device__ __forceinline__ uint32_t pack_bf2(float a, float b) {
    __nv_bfloat162 t = __floats2bfloat162_rn(a, b);
    return *reinterpret_cast<uint32_t*>(&t);
}
__device__ __forceinline__ float bf_hi(float f) {
    return __bfloat162float(__float2bfloat16(f));
}

// ---------------- init: copy x -> scr_a, zero hg ----------------
__global__ void init_kernel(const float* __restrict__ x) {
    int i = blockIdx.x * blockDim.x + threadIdx.x;
    const int ncopy = NN * FIN / 4;
    const int nzero = NG * HD / 4;
    if (i < ncopy) {
        ((float4*)g_scr_a)[i] = ((const float4*)x)[i];
    } else {
        int j = i - ncopy;
        if (j < nzero) ((float4*)g_hg)[j] = make_float4(0.f, 0.f, 0.f, 0.f);
    }
}

// ---------------- weight -> W^T bf16 hi/lo planes ----------------
__global__ void setup_kernel(const float* __restrict__ W1a, const float* __restrict__ W2a,
                             const float* __restrict__ W1b, const float* __restrict__ W2b,
                             const float* __restrict__ W1c, const float* __restrict__ W2c) {
    int b = blockIdx.x;
    int tid = threadIdx.x;
    const float* W;
    __nv_bfloat16 *th, *tl;
    int K;
    switch (b) {
        case 0: W = W1a; th = g_W1a[0]; tl = g_W1a[1]; K = 32;  break;
        case 1: W = W2a; th = g_W2a[0]; tl = g_W2a[1]; K = 128; break;
        case 2: W = W1b; th = g_W1b[0]; tl = g_W1b[1]; K = 128; break;
        case 3: W = W2b; th = g_W2b[0]; tl = g_W2b[1]; K = 128; break;
        case 4: W = W1c; th = g_W1c[0]; tl = g_W1c[1]; K = 128; break;
        default: W = W2c; th = g_W2c[0]; tl = g_W2c[1]; K = 128; break;
    }
    int nel = K * 128;
    for (int i = tid; i < nel; i += 256) {
        int k = i >> 7, n = i & 127;   // W[k][n] row-major
        float w = W[i];
        float hi = bf_hi(w);
        th[n * K + k] = __float2bfloat16(w);
        tl[n * K + k] = __float2bfloat16(w - hi);
    }
}

// ---------------- scatter-add ----------------
template <int DIM>
__global__ void scatter_kernel(const int* __restrict__ ei,
                               const float* __restrict__ h,
                               float* __restrict__ scr) {
    const int CH = DIM / 4;
    long long id = (long long)blockIdx.x * blockDim.x + threadIdx.x;
    int e = (int)(id / CH);
    int c = (int)(id % CH);
    if (e >= NE) return;
    int src = __ldg(&ei[e]);
    int dst = __ldg(&ei[NE + e]);
    float4 v = __ldg(((const float4*)(h + (size_t)src * DIM)) + c);
    atomicAdd(((float4*)(scr + (size_t)dst * DIM)) + c, v);
}

// ---------------- mma phase: acc += Zhi@Whi + Zhi@Wlo + Zlo@Whi ----------------
template <int KS>
__device__ __forceinline__ void do_phase(uint32_t sb, int wrow, int whalf, int lane,
                                         uint32_t WHo, uint32_t WLo, float acc[8][4]) {
#pragma unroll
    for (int ks = 0; ks < KS; ks++) {
        uint32_t arow = wrow + (lane & 15);
        uint32_t acol = ks * 16 + ((lane >> 4) << 3);
        uint32_t ah[4], al[4];
        ldsm4(ah, sb + OFF_ZH + arow * 272 + acol * 2);
        ldsm4(al, sb + OFF_ZL + arow * 272 + acol * 2);
#pragma unroll
        for (int tp = 0; tp < 4; tp++) {
            int n0 = whalf * 64 + tp * 16;
            uint32_t brow = n0 + ((lane >> 4) << 3) + (lane & 7);
            uint32_t bcol = ks * 16 + (((lane >> 3) & 1) << 3);
            uint32_t bh[4], bl[4];
            ldsm4(bh, sb + WHo + brow * 272 + bcol * 2);
            ldsm4(bl, sb + WLo + brow * 272 + bcol * 2);
            mma16816(acc[2 * tp],     ah, bh[0], bh[1]);
            mma16816(acc[2 * tp + 1], ah, bh[2], bh[3]);
            mma16816(acc[2 * tp],     ah, bl[0], bl[1]);
            mma16816(acc[2 * tp + 1], ah, bl[2], bl[3]);
            mma16816(acc[2 * tp],     al, bh[0], bh[1]);
            mma16816(acc[2 * tp + 1], al, bh[2], bh[3]);
        }
    }
}

// ---------------- fused GIN layer on tensor cores ----------------
// K1 = 32 or 128. MODE 0: write h_next+scr_next. MODE 1: pool into g_hg.
template <int K1, int MODE>
__global__ void __launch_bounds__(512, 1)
gin_mma_kernel(const float* __restrict__ in,
               const __nv_bfloat16* __restrict__ W1h, const __nv_bfloat16* __restrict__ W1l,
               const __nv_bfloat16* __restrict__ W2h, const __nv_bfloat16* __restrict__ W2l,
               const float* __restrict__ b1, const float* __restrict__ gg,
               const float* __restrict__ be, const float* __restrict__ rm,
               const float* __restrict__ rv, const float* __restrict__ b2,
               float* __restrict__ h_next, float* __restrict__ scr_next,
               const int* __restrict__ batch) {
    extern __shared__ char smem[];
    float* smul = (float*)(smem);
    float* sadd = (float*)(smem + 512);
    float* sb2  = (float*)(smem + 1024);
    uint32_t sb = smem_u32(smem);

    int tid = threadIdx.x, lane = tid & 31, wid = tid >> 5;
    int wrow = (wid & 7) * 16;    // this warp's row base
    int whalf = wid >> 3;         // n-half 0/1
    int base = blockIdx.x * 128;

    // BN params
    if (tid < 128) {
        float mul = gg[tid] * rsqrtf(rv[tid] + BN_EPS);
        smul[tid] = mul;
        sadd[tid] = (b1[tid] - rm[tid]) * mul + be[tid];
        sb2[tid] = b2[tid];
    }

    // ---- async weight staging: W1 (group 0), W2 (group 1) ----
    const int C1 = K1 / 8;   // 16B chunks per W1 row
    for (int i = tid; i < 128 * C1; i += 512) {
        int n = i / C1, j = i % C1;
        CP16(sb + OFF_W1H + n * 272 + j * 16, (const char*)W1h + n * K1 * 2 + j * 16);
        CP16(sb + OFF_W1L + n * 272 + j * 16, (const char*)W1l + n * K1 * 2 + j * 16);
    }
    CP_COMMIT();
    for (int i = tid; i < 128 * 16; i += 512) {
        int n = i >> 4, j = i & 15;
        CP16(sb + OFF_W2H + n * 272 + j * 16, (const char*)W2h + n * 256 + j * 16);
        CP16(sb + OFF_W2L + n * 272 + j * 16, (const char*)W2l + n * 256 + j * 16);
    }
    CP_COMMIT();

    // ---- stage A into Z buffer as bf16 hi/lo ----
    {
        int row = tid >> 2, q = tid & 3;
        long long node = base + row;
        bool valid = node < NN;
        if (K1 == 128) {
            const float4* src = (const float4*)(in + node * 128 + q * 32);
#pragma unroll
            for (int j = 0; j < 8; j++) {
                float4 v = valid ? __ldg(src + j) : make_float4(0.f, 0.f, 0.f, 0.f);
                int col = q * 32 + j * 4;
                float h0 = bf_hi(v.x), h1 = bf_hi(v.y), h2 = bf_hi(v.z), h3 = bf_hi(v.w);
                *(uint32_t*)(smem + OFF_ZH + row * 272 + col * 2)     = pack_bf2(v.x, v.y);
                *(uint32_t*)(smem + OFF_ZH + row * 272 + col * 2 + 4) = pack_bf2(v.z, v.w);
                *(uint32_t*)(smem + OFF_ZL + row * 272 + col * 2)     = pack_bf2(v.x - h0, v.y - h1);
                *(uint32_t*)(smem + OFF_ZL + row * 272 + col * 2 + 4) = pack_bf2(v.z - h2, v.w - h3);
            }
        } else {
            const float4* src = (const float4*)(in + node * 32 + q * 8);
#pragma unroll
            for (int j = 0; j < 2; j++) {
                float4 v = valid ? __ldg(src + j) : make_float4(0.f, 0.f, 0.f, 0.f);
                int col = q * 8 + j * 4;
                float h0 = bf_hi(v.x), h1 = bf_hi(v.y), h2 = bf_hi(v.z), h3 = bf_hi(v.w);
                *(uint32_t*)(smem + OFF_ZH + row * 272 + col * 2)     = pack_bf2(v.x, v.y);
                *(uint32_t*)(smem + OFF_ZH + row * 272 + col * 2 + 4) = pack_bf2(v.z, v.w);
                *(uint32_t*)(smem + OFF_ZL + row * 272 + col * 2)     = pack_bf2(v.x - h0, v.y - h1);
                *(uint32_t*)(smem + OFF_ZL + row * 272 + col * 2 + 4) = pack_bf2(v.z - h2, v.w - h3);
            }
        }
    }
    CP_WAIT1();          // W1 resident
    __syncthreads();

    // ---- phase 1 ----
    float acc[8][4];
#pragma unroll
    for (int t = 0; t < 8; t++)
#pragma unroll
        for (int j = 0; j < 4; j++) acc[t][j] = 0.f;
    do_phase<K1 / 16>(sb, wrow, whalf, lane, OFF_W1H, OFF_W1L, acc);

    CP_WAIT0();          // W2 resident
    __syncthreads();     // everyone done reading A before Z overwrite

    // ---- epilogue 1: BN + ReLU -> Z (bf16 hi/lo, in place) ----
#pragma unroll
    for (int t = 0; t < 8; t++) {
        int col = whalf * 64 + 8 * t + 2 * (lane & 3);
        float m0 = smul[col], m1 = smul[col + 1];
        float a0 = sadd[col], a1 = sadd[col + 1];
        int r0 = wrow + (lane >> 2), r1 = r0 + 8;
        float f0 = fmaxf(fmaf(acc[t][0], m0, a0), 0.f);
        float f1 = fmaxf(fmaf(acc[t][1], m1, a1), 0.f);
        float f2 = fmaxf(fmaf(acc[t][2], m0, a0), 0.f);
        float f3 = fmaxf(fmaf(acc[t][3], m1, a1), 0.f);
        float h0 = bf_hi(f0), h1 = bf_hi(f1), h2 = bf_hi(f2), h3 = bf_hi(f3);
        *(uint32_t*)(smem + OFF_ZH + r0 * 272 + col * 2) = pack_bf2(f0, f1);
        *(uint32_t*)(smem + OFF_ZL + r0 * 272 + col * 2) = pack_bf2(f0 - h0, f1 - h1);
        *(uint32_t*)(smem + OFF_ZH + r1 * 272 + col * 2) = pack_bf2(f2, f3);
        *(uint32_t*)(smem + OFF_ZL + r1 * 272 + col * 2) = pack_bf2(f2 - h2, f3 - h3);
    }
    __syncthreads();

    // ---- phase 2 ----
#pragma unroll
    for (int t = 0; t < 8; t++)
#pragma unroll
        for (int j = 0; j < 4; j++) acc[t][j] = 0.f;
    do_phase<8>(sb, wrow, whalf, lane, OFF_W2H, OFF_W2L, acc);
    __syncthreads();     // done reading Z; reuse buffer for fp32 output staging

    // ---- epilogue 2: bias + ReLU -> fp32 staging (stride 132 floats) ----
#pragma unroll
    for (int t = 0; t < 8; t++) {
        int col = whalf * 64 + 8 * t + 2 * (lane & 3);
        float bb0 = sb2[col], bb1 = sb2[col + 1];
        int r0 = wrow + (lane >> 2), r1 = r0 + 8;
        float2 v0 = make_float2(fmaxf(acc[t][0] + bb0, 0.f), fmaxf(acc[t][1] + bb1, 0.f));
        float2 v1 = make_float2(fmaxf(acc[t][2] + bb0, 0.f), fmaxf(acc[t][3] + bb1, 0.f));
        *(float2*)(smem + OFF_ZH + r0 * 528 + col * 4) = v0;
        *(float2*)(smem + OFF_ZH + r1 * 528 + col * 4) = v1;
    }
    __syncthreads();

    // ---- global write: coalesced (MODE 0) / pooled atomics (MODE 1) ----
    {
        int c4 = tid & 31;        // 16B chunk = cols 4c4..4c4+3
        int rg = (tid >> 5) * 8;  // 8 rows per thread
        if (MODE == 0) {
#pragma unroll
            for (int rr = 0; rr < 8; rr++) {
                int row = rg + rr;
                long long node = base + row;
                if (node < NN) {
                    float4 v = *(float4*)(smem + OFF_ZH + row * 528 + c4 * 16);
                    *(float4*)(h_next + node * 128 + c4 * 4) = v;
                    *(float4*)(scr_next + node * 128 + c4 * 4) = v;
                }
            }
        } else {
            int prev = -1;
            float4 sum = make_float4(0.f, 0.f, 0.f, 0.f);
#pragma unroll
            for (int rr = 0; rr < 8; rr++) {
                int row = rg + rr;
                long long node = base + row;
                if (node >= NN) break;
                float4 v = *(float4*)(smem + OFF_ZH + row * 528 + c4 * 16);
                int bg = __ldg(&batch[node]);
                if (bg == prev) {
                    sum.x += v.x; sum.y += v.y; sum.z += v.z; sum.w += v.w;
                } else {
                    if (prev >= 0)
                        atomicAdd((float4*)(g_hg + (size_t)prev * 128 + c4 * 4), sum);
                    prev = bg;
                    sum = v;
                }
            }
            if (prev >= 0)
                atomicAdd((float4*)(g_hg + (size_t)prev * 128 + c4 * 4), sum);
        }
    }
}

// ---------------- pooled MLP head ----------------
__global__ void pool_head_kernel(const float* __restrict__ lw1,
                                 const float* __restrict__ lb1,
                                 const float* __restrict__ lw2,
                                 const float* __restrict__ lb2,
                                 float* __restrict__ out) {
    extern __shared__ float psm[];
    float* Ws   = psm;
    float* hrow = psm + HD * HD;
    float* redb = hrow + HD;

    int t = threadIdx.x;
    for (int i = t; i < HD * HD / 4; i += 128)
        ((float4*)Ws)[i] = __ldg(((const float4*)lw1) + i);
    float lb1t = __ldg(&lb1[t]);
    float w2t  = __ldg(&lw2[t]);
    float lb2v = __ldg(&lb2[0]);
    __syncthreads();

    int gbase = blockIdx.x * 8;
    for (int gi = 0; gi < 8; gi++) {
        int g = gbase + gi;
        hrow[t] = g_hg[(size_t)g * HD + t];
        __syncthreads();
        float a = 0.f;
#pragma unroll
        for (int k = 0; k < HD; k++)
            a = fmaf(hrow[k], Ws[k * HD + t], a);
        float p = fmaxf(a + lb1t, 0.f) * w2t;
#pragma unroll
        for (int o = 16; o > 0; o >>= 1)
            p += __shfl_xor_sync(0xffffffffu, p, o);
        if ((t & 31) == 0) redb[t >> 5] = p;
        __syncthreads();
        if (t == 0)
            out[g] = redb[0] + redb[1] + redb[2] + redb[3] + lb2v;
        __syncthreads();
    }
}

// ---------------- launch ----------------
extern "C" void kernel_launch(void* const* d_in, const int* in_sizes, int n_in,
                              void* d_out, int out_size) {
    const float* x   = (const float*)d_in[0];
    const int* ei    = (const int*)d_in[1];
    const int* batch = (const int*)d_in[2];
    const float* W1a = (const float*)d_in[3];
    const float* b1a = (const float*)d_in[4];
    const float* ga  = (const float*)d_in[5];
    const float* bea = (const float*)d_in[6];
    const float* rma = (const float*)d_in[7];
    const float* rva = (const float*)d_in[8];
    const float* W2a = (const float*)d_in[9];
    const float* b2a = (const float*)d_in[10];
    const float* W1b = (const float*)d_in[11];
    const float* b1b = (const float*)d_in[12];
    const float* gb  = (const float*)d_in[13];
    const float* beb = (const float*)d_in[14];
    const float* rmb = (const float*)d_in[15];
    const float* rvb = (const float*)d_in[16];
    const float* W2b = (const float*)d_in[17];
    const float* b2b = (const float*)d_in[18];
    const float* W1c = (const float*)d_in[19];
    const float* b1c = (const float*)d_in[20];
    const float* gc  = (const float*)d_in[21];
    const float* bec = (const float*)d_in[22];
    const float* rmc = (const float*)d_in[23];
    const float* rvc = (const float*)d_in[24];
    const float* W2c = (const float*)d_in[25];
    const float* b2c = (const float*)d_in[26];
    const float* lw1 = (const float*)d_in[27];
    const float* lb1 = (const float*)d_in[28];
    const float* lw2 = (const float*)d_in[29];
    const float* lb2 = (const float*)d_in[30];
    float* out = (float*)d_out;

    float *scr_a, *h1, *scr_b, *h2, *scr_c;
    cudaGetSymbolAddress((void**)&scr_a, g_scr_a);
    cudaGetSymbolAddress((void**)&h1,    g_h1);
    cudaGetSymbolAddress((void**)&scr_b, g_scr_b);
    cudaGetSymbolAddress((void**)&h2,    g_h2);
    cudaGetSymbolAddress((void**)&scr_c, g_scr_c);

    __nv_bfloat16 *Wa1, *Wa2, *Wb1, *Wb2, *Wc1, *Wc2;
    cudaGetSymbolAddress((void**)&Wa1, g_W1a);
    cudaGetSymbolAddress((void**)&Wa2, g_W2a);
    cudaGetSymbolAddress((void**)&Wb1, g_W1b);
    cudaGetSymbolAddress((void**)&Wb2, g_W2b);
    cudaGetSymbolAddress((void**)&Wc1, g_W1c);
    cudaGetSymbolAddress((void**)&Wc2, g_W2c);

    const int smem_p = (HD * HD + HD + 4) * 4;

    cudaFuncSetAttribute(gin_mma_kernel<32, 0>,
                         cudaFuncAttributeMaxDynamicSharedMemorySize, SMEM_TOTAL);
    cudaFuncSetAttribute(gin_mma_kernel<128, 0>,
                         cudaFuncAttributeMaxDynamicSharedMemorySize, SMEM_TOTAL);
    cudaFuncSetAttribute(gin_mma_kernel<128, 1>,
                         cudaFuncAttributeMaxDynamicSharedMemorySize, SMEM_TOTAL);
    cudaFuncSetAttribute(pool_head_kernel,
                         cudaFuncAttributeMaxDynamicSharedMemorySize, smem_p);

    // 1. init + weight conversion
    init_kernel<<<7500, 256>>>(x);
    setup_kernel<<<6, 256>>>(W1a, W2a, W1b, W2b, W1c, W2c);

    // 2. scatter x into scr_a
    scatter_kernel<FIN><<<18750, 256>>>(ei, x, scr_a);

    // 3. layer a
    gin_mma_kernel<32, 0><<<NBLK, 512, SMEM_TOTAL>>>(
        scr_a, Wa1, Wa1 + 128 * 32, Wa2, Wa2 + 128 * 128,
        b1a, ga, bea, rma, rva, b2a, h1, scr_b, nullptr);

    // 4. scatter h1 into scr_b
    scatter_kernel<HD><<<75000, 256>>>(ei, h1, scr_b);

    // 5. layer b
    gin_mma_kernel<128, 0><<<NBLK, 512, SMEM_TOTAL>>>(
        scr_b, Wb1, Wb1 + 128 * 128, Wb2, Wb2 + 128 * 128,
        b1b, gb, beb, rmb, rvb, b2b, h2, scr_c, nullptr);

    // 6. scatter h2 into scr_c
    scatter_kernel<HD><<<75000, 256>>>(ei, h2, scr_c);

    // 7. layer c + fused pool
    gin_mma_kernel<128, 1><<<NBLK, 512, SMEM_TOTAL>>>(
        scr_c, Wc1, Wc1 + 128 * 128, Wc2, Wc2 + 128 * 128,
        b1c, gc, bec, rmc, rvc, b2c, nullptr, nullptr, batch);

    // 8. head MLP
    pool_head_kernel<<<NG / 8, 128, smem_p>>>(lw1, lb1, lw2, lb2, out);
}